// round 2
// baseline (speedup 1.0000x reference)
#include <cuda_runtime.h>

// Constant-memory weight block:
// [0:6)  W1 (3x2)   [6:9)  b1   [9:15) W2 (2x3)   [15:17) b2   [17:19) W3 (1x2)   [19] b3
__constant__ float c_w[20];

__global__ __launch_bounds__(256, 8)
void mlp321_kernel(const float* __restrict__ x,
                   float* __restrict__ out,     // [B]
                   float* __restrict__ h1_out,  // [B,3]
                   float* __restrict__ h2_out,  // [B,2]
                   int n4)                      // B/4
{
    int t = blockIdx.x * blockDim.x + threadIdx.x;
    if (t >= n4) return;

    long long i = (long long)t * 4;   // first row handled by this thread

    // ---- load 4 rows of x (8 floats = 2x float4), streaming hint ----
    const float4* xv = reinterpret_cast<const float4*>(x + 2 * i);
    float4 xa = __ldcs(xv + 0);
    float4 xb = __ldcs(xv + 1);
    float x0[4] = {xa.x, xa.z, xb.x, xb.z};
    float x1[4] = {xa.y, xa.w, xb.y, xb.w};

    float h1v[4][3], h2v[4][2], ov[4];

#pragma unroll
    for (int e = 0; e < 4; e++) {
        // layer 1: [2] -> [3], W1 row-major [3,2]
#pragma unroll
        for (int j = 0; j < 3; j++) {
            float v = fmaf(x0[e], c_w[j * 2 + 0], fmaf(x1[e], c_w[j * 2 + 1], c_w[6 + j]));
            h1v[e][j] = fmaxf(v, 0.0f);
        }
        // layer 2: [3] -> [2], W2 row-major [2,3]
#pragma unroll
        for (int j = 0; j < 2; j++) {
            float v = c_w[15 + j];
#pragma unroll
            for (int k = 0; k < 3; k++) v = fmaf(h1v[e][k], c_w[9 + j * 3 + k], v);
            h2v[e][j] = fmaxf(v, 0.0f);
        }
        // layer 3: [2] -> [1], sigmoid
        float z = fmaf(h2v[e][0], c_w[17], fmaf(h2v[e][1], c_w[18], c_w[19]));
        ov[e] = 1.0f / (1.0f + __expf(-z));
    }

    // ---- stores, all 16B-aligned vector stores, streaming (never re-read) ----
    __stcs(reinterpret_cast<float4*>(out + i),
           make_float4(ov[0], ov[1], ov[2], ov[3]));

    float4* h1p = reinterpret_cast<float4*>(h1_out + 3 * i);
    __stcs(h1p + 0, make_float4(h1v[0][0], h1v[0][1], h1v[0][2], h1v[1][0]));
    __stcs(h1p + 1, make_float4(h1v[1][1], h1v[1][2], h1v[2][0], h1v[2][1]));
    __stcs(h1p + 2, make_float4(h1v[2][2], h1v[3][0], h1v[3][1], h1v[3][2]));

    float4* h2p = reinterpret_cast<float4*>(h2_out + 2 * i);
    __stcs(h2p + 0, make_float4(h2v[0][0], h2v[0][1], h2v[1][0], h2v[1][1]));
    __stcs(h2p + 1, make_float4(h2v[2][0], h2v[2][1], h2v[3][0], h2v[3][1]));
}

extern "C" void kernel_launch(void* const* d_in, const int* in_sizes, int n_in,
                              void* d_out, int out_size)
{
    const float* x = (const float*)d_in[0];

    // Copy the 20 weight/bias floats into constant memory (async D2D memcpys,
    // graph-capturable, deterministic).
    cudaMemcpyToSymbolAsync(c_w, d_in[1], 6 * sizeof(float), 0 * sizeof(float),
                            cudaMemcpyDeviceToDevice, 0);   // W1
    cudaMemcpyToSymbolAsync(c_w, d_in[2], 3 * sizeof(float), 6 * sizeof(float),
                            cudaMemcpyDeviceToDevice, 0);   // b1
    cudaMemcpyToSymbolAsync(c_w, d_in[3], 6 * sizeof(float), 9 * sizeof(float),
                            cudaMemcpyDeviceToDevice, 0);   // W2
    cudaMemcpyToSymbolAsync(c_w, d_in[4], 2 * sizeof(float), 15 * sizeof(float),
                            cudaMemcpyDeviceToDevice, 0);   // b2
    cudaMemcpyToSymbolAsync(c_w, d_in[5], 2 * sizeof(float), 17 * sizeof(float),
                            cudaMemcpyDeviceToDevice, 0);   // W3
    cudaMemcpyToSymbolAsync(c_w, d_in[6], 1 * sizeof(float), 19 * sizeof(float),
                            cudaMemcpyDeviceToDevice, 0);   // b3

    int B = in_sizes[0] / 2;   // x is [B,2]
    float* out    = (float*)d_out;                   // [B]
    float* h1_out = out + B;                         // [B,3]
    float* h2_out = h1_out + (long long)B * 3;       // [B,2]

    int n4 = B / 4;
    int threads = 256;
    int blocks = (n4 + threads - 1) / threads;
    mlp321_kernel<<<blocks, threads>>>(x, out, h1_out, h2_out, n4);
}

// round 3
// speedup vs baseline: 1.1900x; 1.1900x over previous
#include <cuda_runtime.h>
#include <cstdint>

#define ROWS_PER_BLOCK 1024
#define THREADS 256

__device__ __forceinline__ uint32_t smem_u32(const void* p) {
    return (uint32_t)__cvta_generic_to_shared(p);
}

__global__ __launch_bounds__(THREADS, 8)
void mlp321_kernel(const float* __restrict__ x,
                   const float* __restrict__ W1, const float* __restrict__ b1,
                   const float* __restrict__ W2, const float* __restrict__ b2,
                   const float* __restrict__ W3, const float* __restrict__ b3,
                   float* __restrict__ out,     // [B]
                   float* __restrict__ h1_out,  // [B,3]
                   float* __restrict__ h2_out)  // [B,2]
{
    __shared__ __align__(16) float s_out[ROWS_PER_BLOCK];        //  4 KB
    __shared__ __align__(16) float s_h1[ROWS_PER_BLOCK * 3];     // 12 KB
    __shared__ __align__(16) float s_h2[ROWS_PER_BLOCK * 2];     //  8 KB

    int tid = threadIdx.x;
    long long base = (long long)blockIdx.x * ROWS_PER_BLOCK;

    // tiny weights: broadcast L1 hits
    float w1[6], bb1[3], w2[6], bb2[2], w3[2], bb3;
#pragma unroll
    for (int i = 0; i < 6; i++) w1[i] = __ldg(W1 + i);
#pragma unroll
    for (int i = 0; i < 3; i++) bb1[i] = __ldg(b1 + i);
#pragma unroll
    for (int i = 0; i < 6; i++) w2[i] = __ldg(W2 + i);
#pragma unroll
    for (int i = 0; i < 2; i++) bb2[i] = __ldg(b2 + i);
#pragma unroll
    for (int i = 0; i < 2; i++) w3[i] = __ldg(W3 + i);
    bb3 = __ldg(b3);

    // strided row mapping: thread t handles rows t, t+256, t+512, t+768.
    // x loads: warp-contiguous 256B per load. STS: stride-3/2/1 words -> conflict-free.
    float2 xv[4];
#pragma unroll
    for (int r = 0; r < 4; r++) {
        int row = tid + r * THREADS;
        xv[r] = __ldg(reinterpret_cast<const float2*>(x + (base + row) * 2));
    }

#pragma unroll
    for (int r = 0; r < 4; r++) {
        int row = tid + r * THREADS;
        float x0 = xv[r].x, x1 = xv[r].y;

        float h1v[3];
#pragma unroll
        for (int j = 0; j < 3; j++) {
            float v = fmaf(x0, w1[j * 2 + 0], fmaf(x1, w1[j * 2 + 1], bb1[j]));
            h1v[j] = fmaxf(v, 0.0f);
        }
        float h2v[2];
#pragma unroll
        for (int j = 0; j < 2; j++) {
            float v = bb2[j];
#pragma unroll
            for (int k = 0; k < 3; k++) v = fmaf(h1v[k], w2[j * 3 + k], v);
            h2v[j] = fmaxf(v, 0.0f);
        }
        float z = fmaf(h2v[0], w3[0], fmaf(h2v[1], w3[1], bb3));
        float o = 1.0f / (1.0f + __expf(-z));

        s_h1[row * 3 + 0] = h1v[0];
        s_h1[row * 3 + 1] = h1v[1];
        s_h1[row * 3 + 2] = h1v[2];
        s_h2[row * 2 + 0] = h2v[0];
        s_h2[row * 2 + 1] = h2v[1];
        s_out[row] = o;
    }

    // make generic-proxy smem writes visible to the async (TMA) proxy
    asm volatile("fence.proxy.async.shared::cta;" ::: "memory");
    __syncthreads();

    if (tid == 0) {
        uint32_t so = smem_u32(s_out), s1 = smem_u32(s_h1), s2 = smem_u32(s_h2);
        asm volatile(
            "cp.async.bulk.global.shared::cta.bulk_group [%0], [%1], %2;"
            :: "l"(out + base), "r"(so), "r"((uint32_t)(ROWS_PER_BLOCK * 4)) : "memory");
        asm volatile(
            "cp.async.bulk.global.shared::cta.bulk_group [%0], [%1], %2;"
            :: "l"(h1_out + base * 3), "r"(s1), "r"((uint32_t)(ROWS_PER_BLOCK * 12)) : "memory");
        asm volatile(
            "cp.async.bulk.global.shared::cta.bulk_group [%0], [%1], %2;"
            :: "l"(h2_out + base * 2), "r"(s2), "r"((uint32_t)(ROWS_PER_BLOCK * 8)) : "memory");
        asm volatile("cp.async.bulk.commit_group;" ::: "memory");
        asm volatile("cp.async.bulk.wait_group 0;" ::: "memory");
    }
}

extern "C" void kernel_launch(void* const* d_in, const int* in_sizes, int n_in,
                              void* d_out, int out_size)
{
    const float* x  = (const float*)d_in[0];
    const float* W1 = (const float*)d_in[1];
    const float* b1 = (const float*)d_in[2];
    const float* W2 = (const float*)d_in[3];
    const float* b2 = (const float*)d_in[4];
    const float* W3 = (const float*)d_in[5];
    const float* b3 = (const float*)d_in[6];

    int B = in_sizes[0] / 2;   // x is [B,2]
    float* out    = (float*)d_out;                 // [B]
    float* h1_out = out + B;                       // [B,3]
    float* h2_out = h1_out + (long long)B * 3;     // [B,2]

    int blocks = B / ROWS_PER_BLOCK;               // B = 8388608 -> 8192
    mlp321_kernel<<<blocks, THREADS>>>(x, W1, b1, W2, b2, W3, b3,
                                       out, h1_out, h2_out);
}

// round 4
// speedup vs baseline: 1.1996x; 1.0080x over previous
#include <cuda_runtime.h>
#include <cstdint>

#define ROWS_PER_BLOCK 2048
#define THREADS 512

__device__ __forceinline__ uint32_t smem_u32(const void* p) {
    return (uint32_t)__cvta_generic_to_shared(p);
}

__global__ __launch_bounds__(THREADS, 4)
void mlp321_kernel(const float* __restrict__ x,
                   const float* __restrict__ W1, const float* __restrict__ b1,
                   const float* __restrict__ W2, const float* __restrict__ b2,
                   const float* __restrict__ W3, const float* __restrict__ b3,
                   float* __restrict__ out,     // [B]
                   float* __restrict__ h1_out,  // [B,3]
                   float* __restrict__ h2_out)  // [B,2]
{
    __shared__ __align__(16) float s_out[ROWS_PER_BLOCK];        //  8 KB
    __shared__ __align__(16) float s_h1[ROWS_PER_BLOCK * 3];     // 24 KB
    __shared__ __align__(16) float s_h2[ROWS_PER_BLOCK * 2];     // 16 KB

    int tid = threadIdx.x;
    long long base = (long long)blockIdx.x * ROWS_PER_BLOCK;

    // tiny weights: broadcast L1 hits
    float w1[6], bb1[3], w2[6], bb2[2], w3[2], bb3;
#pragma unroll
    for (int i = 0; i < 6; i++) w1[i] = __ldg(W1 + i);
#pragma unroll
    for (int i = 0; i < 3; i++) bb1[i] = __ldg(b1 + i);
#pragma unroll
    for (int i = 0; i < 6; i++) w2[i] = __ldg(W2 + i);
#pragma unroll
    for (int i = 0; i < 2; i++) bb2[i] = __ldg(b2 + i);
#pragma unroll
    for (int i = 0; i < 2; i++) w3[i] = __ldg(W3 + i);
    bb3 = __ldg(b3);

    // thread t handles 4 consecutive rows: 4t .. 4t+3 (within block)
    int r0 = tid * 4;

    // ---- load 4 rows of x: 8 floats = 2x LDG.128, fully coalesced ----
    const float4* xv = reinterpret_cast<const float4*>(x + (base + r0) * 2);
    float4 xa = __ldg(xv + 0);
    float4 xb = __ldg(xv + 1);
    float x0[4] = {xa.x, xa.z, xb.x, xb.z};
    float x1[4] = {xa.y, xa.w, xb.y, xb.w};

    float h1v[4][3], h2v[4][2], ov[4];

#pragma unroll
    for (int e = 0; e < 4; e++) {
        // layer 1: [2] -> [3]
#pragma unroll
        for (int j = 0; j < 3; j++) {
            float v = fmaf(x0[e], w1[j * 2 + 0], fmaf(x1[e], w1[j * 2 + 1], bb1[j]));
            h1v[e][j] = fmaxf(v, 0.0f);
        }
        // layer 2: [3] -> [2]
#pragma unroll
        for (int j = 0; j < 2; j++) {
            float v = bb2[j];
#pragma unroll
            for (int k = 0; k < 3; k++) v = fmaf(h1v[e][k], w2[j * 3 + k], v);
            h2v[e][j] = fmaxf(v, 0.0f);
        }
        // layer 3 + sigmoid
        float z = fmaf(h2v[e][0], w3[0], fmaf(h2v[e][1], w3[1], bb3));
        ov[e] = 1.0f / (1.0f + __expf(-z));
    }

    // ---- vector STS into smem staging ----
    // out: 4 contiguous floats at word 4t (contiguous across lanes)
    reinterpret_cast<float4*>(s_out + r0)[0] = make_float4(ov[0], ov[1], ov[2], ov[3]);

    // h1: 12 contiguous floats at word 12t (stride-48B: conflict-free per phase)
    float4* h1p = reinterpret_cast<float4*>(s_h1 + r0 * 3);
    h1p[0] = make_float4(h1v[0][0], h1v[0][1], h1v[0][2], h1v[1][0]);
    h1p[1] = make_float4(h1v[1][1], h1v[1][2], h1v[2][0], h1v[2][1]);
    h1p[2] = make_float4(h1v[2][2], h1v[3][0], h1v[3][1], h1v[3][2]);

    // h2: 8 contiguous floats at word 8t
    float4* h2p = reinterpret_cast<float4*>(s_h2 + r0 * 2);
    h2p[0] = make_float4(h2v[0][0], h2v[0][1], h2v[1][0], h2v[1][1]);
    h2p[1] = make_float4(h2v[2][0], h2v[2][1], h2v[3][0], h2v[3][1]);

    // make generic-proxy smem writes visible to the async (TMA) proxy
    asm volatile("fence.proxy.async.shared::cta;" ::: "memory");
    __syncthreads();

    if (tid == 0) {
        uint32_t so = smem_u32(s_out), s1 = smem_u32(s_h1), s2 = smem_u32(s_h2);
        asm volatile(
            "cp.async.bulk.global.shared::cta.bulk_group [%0], [%1], %2;"
            :: "l"(out + base), "r"(so), "r"((uint32_t)(ROWS_PER_BLOCK * 4)) : "memory");
        asm volatile(
            "cp.async.bulk.global.shared::cta.bulk_group [%0], [%1], %2;"
            :: "l"(h1_out + base * 3), "r"(s1), "r"((uint32_t)(ROWS_PER_BLOCK * 12)) : "memory");
        asm volatile(
            "cp.async.bulk.global.shared::cta.bulk_group [%0], [%1], %2;"
            :: "l"(h2_out + base * 2), "r"(s2), "r"((uint32_t)(ROWS_PER_BLOCK * 8)) : "memory");
        asm volatile("cp.async.bulk.commit_group;" ::: "memory");
        asm volatile("cp.async.bulk.wait_group 0;" ::: "memory");
    }
}

extern "C" void kernel_launch(void* const* d_in, const int* in_sizes, int n_in,
                              void* d_out, int out_size)
{
    const float* x  = (const float*)d_in[0];
    const float* W1 = (const float*)d_in[1];
    const float* b1 = (const float*)d_in[2];
    const float* W2 = (const float*)d_in[3];
    const float* b2 = (const float*)d_in[4];
    const float* W3 = (const float*)d_in[5];
    const float* b3 = (const float*)d_in[6];

    int B = in_sizes[0] / 2;   // x is [B,2]
    float* out    = (float*)d_out;                 // [B]
    float* h1_out = out + B;                       // [B,3]
    float* h2_out = h1_out + (long long)B * 3;     // [B,2]

    int blocks = B / ROWS_PER_BLOCK;               // 8388608 / 2048 = 4096
    mlp321_kernel<<<blocks, THREADS>>>(x, W1, b1, W2, b2, W3, b3,
                                       out, h1_out, h2_out);
}

// round 5
// speedup vs baseline: 1.2085x; 1.0074x over previous
#include <cuda_runtime.h>
#include <cstdint>

#define THREADS 256
#define WARPS 8
#define ROWS_PER_WARP 128
#define ROWS_PER_BLOCK (WARPS * ROWS_PER_WARP)   // 1024

__device__ __forceinline__ uint32_t smem_u32(const void* p) {
    return (uint32_t)__cvta_generic_to_shared(p);
}

__global__ __launch_bounds__(THREADS, 8)
void mlp321_kernel(const float* __restrict__ x,
                   const float* __restrict__ W1, const float* __restrict__ b1,
                   const float* __restrict__ W2, const float* __restrict__ b2,
                   const float* __restrict__ W3, const float* __restrict__ b3,
                   float* __restrict__ out,     // [B]
                   float* __restrict__ h1_out,  // [B,3]
                   float* __restrict__ h2_out)  // [B,2]
{
    // per-warp staging slices (each contiguous, 16B-aligned)
    __shared__ __align__(16) float s_out[WARPS][ROWS_PER_WARP];      // 512 B /warp
    __shared__ __align__(16) float s_h1[WARPS][ROWS_PER_WARP * 3];   // 1536 B /warp
    __shared__ __align__(16) float s_h2[WARPS][ROWS_PER_WARP * 2];   // 1024 B /warp

    int tid  = threadIdx.x;
    int wid  = tid >> 5;
    int lane = tid & 31;

    long long wbase = (long long)blockIdx.x * ROWS_PER_BLOCK + wid * ROWS_PER_WARP;

    // tiny weights: broadcast L1 hits
    float w1[6], bb1[3], w2[6], bb2[2], w3[2], bb3;
#pragma unroll
    for (int i = 0; i < 6; i++) w1[i] = __ldg(W1 + i);
#pragma unroll
    for (int i = 0; i < 3; i++) bb1[i] = __ldg(b1 + i);
#pragma unroll
    for (int i = 0; i < 6; i++) w2[i] = __ldg(W2 + i);
#pragma unroll
    for (int i = 0; i < 2; i++) bb2[i] = __ldg(b2 + i);
#pragma unroll
    for (int i = 0; i < 2; i++) w3[i] = __ldg(W3 + i);
    bb3 = __ldg(b3);

    // lane handles 4 consecutive rows within the warp's 128-row slice
    int r0 = lane * 4;

    // ---- load 4 rows of x: 2x LDG.128, warp covers 1024B contiguous ----
    const float4* xv = reinterpret_cast<const float4*>(x + (wbase + r0) * 2);
    float4 xa = __ldg(xv + 0);
    float4 xb = __ldg(xv + 1);
    float x0[4] = {xa.x, xa.z, xb.x, xb.z};
    float x1[4] = {xa.y, xa.w, xb.y, xb.w};

    float h1v[4][3], h2v[4][2], ov[4];

#pragma unroll
    for (int e = 0; e < 4; e++) {
#pragma unroll
        for (int j = 0; j < 3; j++) {
            float v = fmaf(x0[e], w1[j * 2 + 0], fmaf(x1[e], w1[j * 2 + 1], bb1[j]));
            h1v[e][j] = fmaxf(v, 0.0f);
        }
#pragma unroll
        for (int j = 0; j < 2; j++) {
            float v = bb2[j];
#pragma unroll
            for (int k = 0; k < 3; k++) v = fmaf(h1v[e][k], w2[j * 3 + k], v);
            h2v[e][j] = fmaxf(v, 0.0f);
        }
        float z = fmaf(h2v[e][0], w3[0], fmaf(h2v[e][1], w3[1], bb3));
        ov[e] = 1.0f / (1.0f + __expf(-z));
    }

    // ---- vector STS into this warp's slice ----
    reinterpret_cast<float4*>(&s_out[wid][r0])[0] =
        make_float4(ov[0], ov[1], ov[2], ov[3]);

    float4* h1p = reinterpret_cast<float4*>(&s_h1[wid][r0 * 3]);
    h1p[0] = make_float4(h1v[0][0], h1v[0][1], h1v[0][2], h1v[1][0]);
    h1p[1] = make_float4(h1v[1][1], h1v[1][2], h1v[2][0], h1v[2][1]);
    h1p[2] = make_float4(h1v[2][2], h1v[3][0], h1v[3][1], h1v[3][2]);

    float4* h2p = reinterpret_cast<float4*>(&s_h2[wid][r0 * 2]);
    h2p[0] = make_float4(h2v[0][0], h2v[0][1], h2v[1][0], h2v[1][1]);
    h2p[1] = make_float4(h2v[2][0], h2v[2][1], h2v[3][0], h2v[3][1]);

    // order generic-proxy smem writes before async-proxy reads, warp-local sync
    asm volatile("fence.proxy.async.shared::cta;" ::: "memory");
    __syncwarp();

    // elected lane issues this warp's three bulk stores — no block barrier
    if (lane == 0) {
        uint32_t so = smem_u32(&s_out[wid][0]);
        uint32_t s1 = smem_u32(&s_h1[wid][0]);
        uint32_t s2 = smem_u32(&s_h2[wid][0]);
        asm volatile(
            "cp.async.bulk.global.shared::cta.bulk_group [%0], [%1], %2;"
            :: "l"(out + wbase), "r"(so), "r"((uint32_t)(ROWS_PER_WARP * 4)) : "memory");
        asm volatile(
            "cp.async.bulk.global.shared::cta.bulk_group [%0], [%1], %2;"
            :: "l"(h1_out + wbase * 3), "r"(s1), "r"((uint32_t)(ROWS_PER_WARP * 12)) : "memory");
        asm volatile(
            "cp.async.bulk.global.shared::cta.bulk_group [%0], [%1], %2;"
            :: "l"(h2_out + wbase * 2), "r"(s2), "r"((uint32_t)(ROWS_PER_WARP * 8)) : "memory");
        asm volatile("cp.async.bulk.commit_group;" ::: "memory");
        // only wait for smem reads (source safety); global writes drain on their own
        asm volatile("cp.async.bulk.wait_group.read 0;" ::: "memory");
    }
}

extern "C" void kernel_launch(void* const* d_in, const int* in_sizes, int n_in,
                              void* d_out, int out_size)
{
    const float* x  = (const float*)d_in[0];
    const float* W1 = (const float*)d_in[1];
    const float* b1 = (const float*)d_in[2];
    const float* W2 = (const float*)d_in[3];
    const float* b2 = (const float*)d_in[4];
    const float* W3 = (const float*)d_in[5];
    const float* b3 = (const float*)d_in[6];

    int B = in_sizes[0] / 2;   // x is [B,2]
    float* out    = (float*)d_out;                 // [B]
    float* h1_out = out + B;                       // [B,3]
    float* h2_out = h1_out + (long long)B * 3;     // [B,2]

    int blocks = B / ROWS_PER_BLOCK;               // 8388608 / 1024 = 8192
    mlp321_kernel<<<blocks, THREADS>>>(x, W1, b1, W2, b2, W3, b3,
                                       out, h1_out, h2_out);
}